// round 2
// baseline (speedup 1.0000x reference)
#include <cuda_runtime.h>
#include <math.h>

#define D_DIM   10000
#define LVL     100
#define T_STEPS 2048
#define TERMS   2046          // T - 3 + 1
#define NCHUNK  27
#define TCHUNK  76            // 27*76 = 2052 >= 2046
#define NTILE   27            // 81 warps / 3 warps-per-block
#define TILE_W  400           // padded tile width (bytes), 16B-aligned loads + <=12B skew
#define WARPS_PB 3
#define THREADS_PB 96
#define EXT_W   10512         // D + 512, circularly extended & shifted by 4; %16==0
#define PART_STRIDE 10048

// ---------------- scratch (static device globals; no allocation) ----------------
__device__ unsigned char g_lwext[LVL * EXT_W];     // ext[row][j] = (LW[row][(j-4) mod D] > 0)
__device__ unsigned char g_keys01[4 * D_DIM];      // (keys_hv > 0)
__device__ int4          g_idx4[T_STEPS];          // per-t levels, pre-scaled by TILE_W
__device__ int           g_partial[NCHUNK * PART_STRIDE];
__device__ float         g_comb[D_DIM];

__constant__ int c_CF[29] = {547,548,549,551,554,556,557,558,559,560,561,562,563,565,
                             566,567,570,576,580,581,582,583,584,585,588,593,598,599,600};

// ---------------- merged prep kernel ----------------
__device__ __forceinline__ int level_of(float x) {
    x = fminf(fmaxf(x, 0.0f), 1.0f);
    float r = rintf(x * 99.0f);          // round-half-to-even, matches jnp.round
    int i = (int)r;
    i = i < 0 ? 0 : (i > 99 ? 99 : i);
    return i;
}

__global__ void k_prep(const float* __restrict__ signals,
                       const float* __restrict__ keys,
                       const float* __restrict__ lw) {
    int i = blockIdx.x * blockDim.x + threadIdx.x;
    if (i < LVL * EXT_W) {
        int row = i / EXT_W;
        int col = i - row * EXT_W;
        int src = col - 4;
        if (src < 0) src += D_DIM;
        else if (src >= D_DIM) src -= D_DIM;
        g_lwext[i] = (lw[row * D_DIM + src] > 0.0f) ? 1 : 0;
    }
    if (i < 4 * D_DIM) {
        g_keys01[i] = (keys[i] > 0.0f) ? 1 : 0;
    }
    if (i < T_STEPS) {
        float4 sg = ((const float4*)signals)[i];
        g_idx4[i] = make_int4(level_of(sg.x) * TILE_W, level_of(sg.y) * TILE_W,
                              level_of(sg.z) * TILE_W, level_of(sg.w) * TILE_W);
    }
}

// ---------------- comb kernel: warp per d, all 6 k-chains interleaved ----------------
__global__ void k_comb(const float* __restrict__ feat,
                       const float* __restrict__ feat_w,
                       const float* __restrict__ feat_b,
                       const float* __restrict__ mfcc_w,
                       const float* __restrict__ mfcc_b) {
    int lane = threadIdx.x & 31;
    int wib  = threadIdx.x >> 5;
    int d = blockIdx.x * 8 + wib;
    if (d >= D_DIM) return;

    // 6 MFCC sinusoid projections, loads + reductions fully interleaved
    float p[6];
    #pragma unroll
    for (int k = 0; k < 6; k++) {
        const float* wrow = mfcc_w + ((size_t)(k * D_DIM + d)) * 91;
        const float* frow = feat + k * 91;
        float s = wrow[lane] * frow[lane];                 // lane < 32 <= 91
        s += wrow[lane + 32] * frow[lane + 32];            // lane+32 <= 63 < 91
        if (lane + 64 < 91) s += wrow[lane + 64] * frow[lane + 64];
        p[k] = s;
    }
    #pragma unroll
    for (int o = 16; o > 0; o >>= 1) {
        #pragma unroll
        for (int k = 0; k < 6; k++) p[k] += __shfl_xor_sync(0xffffffffu, p[k], o);
    }
    float mfcc_hv = 1.0f;
    #pragma unroll
    for (int k = 0; k < 6; k++) {
        float b = mfcc_b[k * D_DIM + d];
        mfcc_hv *= cosf(p[k] + b) * sinf(p[k]);
    }

    __shared__ float fhv_sm[8][32];
    if (lane < 29) {
        float sel  = feat[c_CF[lane] - 1];
        float wv   = feat_w[lane * D_DIM + d];
        float bv   = feat_b[lane * D_DIM + d];
        float proj = sel * wv;
        fhv_sm[wib][lane] = cosf(proj + bv) * sinf(proj);
    }
    __syncwarp();
    if (lane == 0) {
        const float* h = fhv_sm[wib];
        float comb =
              h[0]  * h[8]  * h[13]
            + h[1]  * h[9]  * h[14]
            + h[2]  * h[10] * h[15]
            + h[3]  * h[4]
            + h[5] * h[7] * h[22] * h[6] * h[23] * h[19] * h[18]
                   * h[20] * h[21] * h[26] * h[28] * h[27]
            + h[11] + h[12]
            + h[16] * h[24]
            + h[17] + h[25]
            + mfcc_hv;
        g_comb[d] = comb;
    }
}

// ---------------- main n-gram kernel ----------------
// Bytewise sign algebra: b01 = (x>0); lw*key = 1-2*(bl^bk); per_t = 4-2*s, s=sum_c xor.
// With u = s-2, per_t = -2u, so ngram term = -8 * uA*uB*uC. All exact integers.
__device__ __forceinline__ void load_u(const unsigned char* lp, const int4 iq,
                                       int kw0, int kw1, int kw2, int kw3, int* u) {
    int x0 = *(const int*)(lp + iq.x) ^ kw0;
    int x1 = *(const int*)(lp + iq.y) ^ kw1;
    int x2 = *(const int*)(lp + iq.z) ^ kw2;
    int x3 = *(const int*)(lp + iq.w) ^ kw3;
    int sp = x0 + x1 + x2 + x3;       // bytewise sums, each <= 4, no carries
    u[0] = ( sp        & 0xFF) - 2;
    u[1] = ((sp >> 8 ) & 0xFF) - 2;
    u[2] = ((sp >> 16) & 0xFF) - 2;
    u[3] = ( sp >> 24        ) - 2;
}

__global__ __launch_bounds__(THREADS_PB) void k_main() {
    __shared__ unsigned char lw_sm[LVL * TILE_W];   // 40000 B
    __shared__ int4 idx_sm[TCHUNK + 2];

    int tb = blockIdx.x;     // column tile
    int s  = blockIdx.y;     // t-chunk
    int tid = threadIdx.x;
    int w = tid >> 5, l = tid & 31;

    // Load level tile, 16B vectorized (base2 aligned, ofs = skew within tile)
    int base  = 372 * tb;    // into ext array (already shifted by 4)
    int ofs   = base & 15;
    int base2 = base - ofs;
    {
        int4* dst = (int4*)lw_sm;
        #pragma unroll 4
        for (int i = tid; i < LVL * (TILE_W / 16); i += THREADS_PB) {
            int row = i / (TILE_W / 16);
            int c   = i - row * (TILE_W / 16);
            dst[i] = *(const int4*)(g_lwext + row * EXT_W + base2 + 16 * c);
        }
    }
    int ts = s * TCHUNK;
    int te = ts + TCHUNK; if (te > TERMS) te = TERMS;
    int nt = te - ts;                      // #terms this chunk (>= 1)
    for (int i = tid; i < nt + 2; i += THREADS_PB) idx_sm[i] = g_idx4[ts + i];
    __syncthreads();

    int g = WARPS_PB * tb + w;             // global warp id (column group)
    // this lane's 4 stream columns start at real col (124g - 4 + 4l) mod D
    int v = 124 * g - 4 + 4 * l;
    if (v < 0) v += D_DIM;
    if (v >= D_DIM) v -= D_DIM;
    int kw0 = *(const int*)(g_keys01 + 0 * D_DIM + v);
    int kw1 = *(const int*)(g_keys01 + 1 * D_DIM + v);
    int kw2 = *(const int*)(g_keys01 + 2 * D_DIM + v);
    int kw3 = *(const int*)(g_keys01 + 3 * D_DIM + v);

    const unsigned char* lp = lw_sm + (ofs + 124 * w + 4 * l);

    int p1[4], p2[4], cur[4];
    int acc[4] = {0, 0, 0, 0};
    load_u(lp, idx_sm[0], kw0, kw1, kw2, kw3, p2);   // u(ts)
    load_u(lp, idx_sm[1], kw0, kw1, kw2, kw3, p1);   // u(ts+1)

    #pragma unroll 3
    for (int i = 2; i < nt + 2; i++) {
        load_u(lp, idx_sm[i], kw0, kw1, kw2, kw3, cur);   // u(ts+i)
        // emit term(ts+i-2): u_{c-2}(t) * u_{c-1}(t+1) * u_c(t+2)
        int a0 = __shfl_up_sync(0xffffffffu, p2[2], 1);
        int a1 = __shfl_up_sync(0xffffffffu, p2[3], 1);
        int b0 = __shfl_up_sync(0xffffffffu, p1[3], 1);
        acc[0] += a0    * b0    * cur[0];
        acc[1] += a1    * p1[0] * cur[1];
        acc[2] += p2[0] * p1[1] * cur[2];
        acc[3] += p2[1] * p1[2] * cur[3];
        p2[0] = p1[0]; p2[1] = p1[1]; p2[2] = p1[2]; p2[3] = p1[3];
        p1[0] = cur[0]; p1[1] = cur[1]; p1[2] = cur[2]; p1[3] = cur[3];
    }

    if (l >= 1) {                           // lane 0 is halo-only
        int obase = 124 * g + 4 * (l - 1);
        int* prow = g_partial + s * PART_STRIDE;
        #pragma unroll
        for (int j = 0; j < 4; j++) {
            int oc = obase + j;
            if (oc < D_DIM) prow[oc] = acc[j];
        }
    }
}

// ---------------- final reduce + quantize ----------------
__global__ void k_final(float* __restrict__ out) {
    int d = blockIdx.x * blockDim.x + threadIdx.x;
    if (d >= D_DIM) return;
    int sum = 0;
    #pragma unroll
    for (int c = 0; c < NCHUNK; c++) sum += g_partial[c * PART_STRIDE + d];
    float sample = -8.0f * (float)sum;      // exact: |.| < 2^24
    float x = sample * g_comb[d];
    out[d] = (x > 0.0f) ? 1.0f : -1.0f;
}

// ---------------- launch ----------------
extern "C" void kernel_launch(void* const* d_in, const int* in_sizes, int n_in,
                              void* d_out, int out_size) {
    const float* signals = (const float*)d_in[0];
    const float* feat    = (const float*)d_in[1];
    const float* keys_hv = (const float*)d_in[2];
    const float* lw      = (const float*)d_in[3];
    const float* feat_w  = (const float*)d_in[4];
    const float* feat_b  = (const float*)d_in[5];
    const float* mfcc_w  = (const float*)d_in[6];
    const float* mfcc_b  = (const float*)d_in[7];
    float* out = (float*)d_out;

    k_prep  <<<(LVL * EXT_W + 255) / 256, 256>>>(signals, keys_hv, lw);
    k_comb  <<<(D_DIM + 7) / 8, 256>>>(feat, feat_w, feat_b, mfcc_w, mfcc_b);
    k_main  <<<dim3(NTILE, NCHUNK), THREADS_PB>>>();
    k_final <<<(D_DIM + 255) / 256, 256>>>(out);
}

// round 3
// speedup vs baseline: 1.2350x; 1.2350x over previous
#include <cuda_runtime.h>
#include <math.h>

#define D_DIM   10000
#define LVL     100
#define T_STEPS 2048
#define TERMS   2046          // T - 3 + 1
#define NCHUNK  27
#define TCHUNK  76            // 27*76 = 2052 >= 2046
#define NTILE   27            // 81 warps / 3 warps-per-block
#define TILE_W  400           // padded tile width (bytes)
#define WARPS_PB 3
#define THREADS_PB 96
#define EXT_W   10512         // D + 512, circularly extended & shifted by 4; %16==0
#define COMB_BLOCKS 1250      // D_DIM/8
#define PREP_BLOCKS 4107      // ceil(LVL*EXT_W/256)

// ---------------- scratch (static device globals; no allocation) ----------------
__device__ unsigned char g_lwext[LVL * EXT_W];     // ext[row][j] = (LW[row][(j-4) mod D] > 0)
__device__ unsigned char g_keys01[4 * D_DIM];      // (keys_hv > 0)
__device__ int4          g_idx4[T_STEPS];          // per-t levels, pre-scaled by TILE_W
__device__ int           g_sum[D_DIM];             // exact integer accumulator
__device__ float         g_comb[D_DIM];

__constant__ int c_CF[29] = {547,548,549,551,554,556,557,558,559,560,561,562,563,565,
                             566,567,570,576,580,581,582,583,584,585,588,593,598,599,600};

// ---------------- merged pre kernel: comb blocks first, then prep blocks ----------------
__device__ __forceinline__ int level_of(float x) {
    x = fminf(fmaxf(x, 0.0f), 1.0f);
    float r = rintf(x * 99.0f);          // round-half-to-even, matches jnp.round
    int i = (int)r;
    i = i < 0 ? 0 : (i > 99 ? 99 : i);
    return i;
}

__global__ void k_pre(const float* __restrict__ signals,
                      const float* __restrict__ keys,
                      const float* __restrict__ lw,
                      const float* __restrict__ feat,
                      const float* __restrict__ feat_w,
                      const float* __restrict__ feat_b,
                      const float* __restrict__ mfcc_w,
                      const float* __restrict__ mfcc_b) {
    if (blockIdx.x < COMB_BLOCKS) {
        // ---- comb: warp per d, all 6 MFCC chains interleaved ----
        int lane = threadIdx.x & 31;
        int wib  = threadIdx.x >> 5;
        int d = blockIdx.x * 8 + wib;
        if (d >= D_DIM) return;

        float p[6];
        #pragma unroll
        for (int k = 0; k < 6; k++) {
            const float* wrow = mfcc_w + ((size_t)(k * D_DIM + d)) * 91;
            const float* frow = feat + k * 91;
            float s = wrow[lane] * frow[lane];
            s += wrow[lane + 32] * frow[lane + 32];
            if (lane + 64 < 91) s += wrow[lane + 64] * frow[lane + 64];
            p[k] = s;
        }
        #pragma unroll
        for (int o = 16; o > 0; o >>= 1) {
            #pragma unroll
            for (int k = 0; k < 6; k++) p[k] += __shfl_xor_sync(0xffffffffu, p[k], o);
        }
        float mfcc_hv = 1.0f;
        #pragma unroll
        for (int k = 0; k < 6; k++) {
            float b = mfcc_b[k * D_DIM + d];
            mfcc_hv *= cosf(p[k] + b) * sinf(p[k]);
        }

        __shared__ float fhv_sm[8][32];
        if (lane < 29) {
            float sel  = feat[c_CF[lane] - 1];
            float wv   = feat_w[lane * D_DIM + d];
            float bv   = feat_b[lane * D_DIM + d];
            float proj = sel * wv;
            fhv_sm[wib][lane] = cosf(proj + bv) * sinf(proj);
        }
        __syncwarp();
        if (lane == 0) {
            const float* h = fhv_sm[wib];
            float comb =
                  h[0]  * h[8]  * h[13]
                + h[1]  * h[9]  * h[14]
                + h[2]  * h[10] * h[15]
                + h[3]  * h[4]
                + h[5] * h[7] * h[22] * h[6] * h[23] * h[19] * h[18]
                       * h[20] * h[21] * h[26] * h[28] * h[27]
                + h[11] + h[12]
                + h[16] * h[24]
                + h[17] + h[25]
                + mfcc_hv;
            g_comb[d] = comb;
        }
    } else {
        // ---- prep ----
        int i = (blockIdx.x - COMB_BLOCKS) * blockDim.x + threadIdx.x;
        if (i < LVL * EXT_W) {
            int row = i / EXT_W;
            int col = i - row * EXT_W;
            int src = col - 4;
            if (src < 0) src += D_DIM;
            else if (src >= D_DIM) src -= D_DIM;
            g_lwext[i] = (lw[row * D_DIM + src] > 0.0f) ? 1 : 0;
        }
        if (i < 4 * D_DIM) {
            g_keys01[i] = (keys[i] > 0.0f) ? 1 : 0;
        }
        if (i < D_DIM) {
            g_sum[i] = 0;
        }
        if (i < T_STEPS) {
            float4 sg = ((const float4*)signals)[i];
            g_idx4[i] = make_int4(level_of(sg.x) * TILE_W, level_of(sg.y) * TILE_W,
                                  level_of(sg.z) * TILE_W, level_of(sg.w) * TILE_W);
        }
    }
}

// ---------------- main n-gram kernel ----------------
// Bytewise sign algebra: b01 = (x>0); lw*key = 1-2*(bl^bk); per_t = 4-2*s, s=sum_c xor.
// With u = s-2, per_t = -2u, so ngram term = -8 * uA*uB*uC. All exact integers.
__device__ __forceinline__ void load_u(const unsigned char* lp, const int4 iq,
                                       int kw0, int kw1, int kw2, int kw3, int* u) {
    int x0 = *(const int*)(lp + iq.x) ^ kw0;
    int x1 = *(const int*)(lp + iq.y) ^ kw1;
    int x2 = *(const int*)(lp + iq.z) ^ kw2;
    int x3 = *(const int*)(lp + iq.w) ^ kw3;
    int sp = x0 + x1 + x2 + x3;       // bytewise sums, each <= 4, no carries
    u[0] = ( sp        & 0xFF) - 2;
    u[1] = ((sp >> 8 ) & 0xFF) - 2;
    u[2] = ((sp >> 16) & 0xFF) - 2;
    u[3] = ( sp >> 24        ) - 2;
}

__global__ __launch_bounds__(THREADS_PB) void k_main() {
    __shared__ unsigned char lw_sm[LVL * TILE_W];   // 40000 B
    __shared__ int4 idx_sm[TCHUNK + 2];

    int tb = blockIdx.x;     // column tile
    int s  = blockIdx.y;     // t-chunk
    int tid = threadIdx.x;
    int w = tid >> 5, l = tid & 31;

    // Load level tile, 16B vectorized (base2 aligned, ofs = skew within tile)
    int base  = 372 * tb;    // into ext array (already shifted by 4)
    int ofs   = base & 15;
    int base2 = base - ofs;
    {
        int4* dst = (int4*)lw_sm;
        #pragma unroll 4
        for (int i = tid; i < LVL * (TILE_W / 16); i += THREADS_PB) {
            int row = i / (TILE_W / 16);
            int c   = i - row * (TILE_W / 16);
            dst[i] = *(const int4*)(g_lwext + row * EXT_W + base2 + 16 * c);
        }
    }
    int ts = s * TCHUNK;
    int te = ts + TCHUNK; if (te > TERMS) te = TERMS;
    int nt = te - ts;                      // #terms this chunk (>= 1)
    for (int i = tid; i < nt + 2; i += THREADS_PB) idx_sm[i] = g_idx4[ts + i];
    __syncthreads();

    int g = WARPS_PB * tb + w;             // global warp id (column group)
    // this lane's 4 stream columns start at real col (124g - 4 + 4l) mod D
    int v = 124 * g - 4 + 4 * l;
    if (v < 0) v += D_DIM;
    if (v >= D_DIM) v -= D_DIM;
    int kw0 = *(const int*)(g_keys01 + 0 * D_DIM + v);
    int kw1 = *(const int*)(g_keys01 + 1 * D_DIM + v);
    int kw2 = *(const int*)(g_keys01 + 2 * D_DIM + v);
    int kw3 = *(const int*)(g_keys01 + 3 * D_DIM + v);

    const unsigned char* lp = lw_sm + (ofs + 124 * w + 4 * l);

    int p1[4], p2[4], cur[4];
    int acc[4] = {0, 0, 0, 0};
    load_u(lp, idx_sm[0], kw0, kw1, kw2, kw3, p2);   // u(ts)
    load_u(lp, idx_sm[1], kw0, kw1, kw2, kw3, p1);   // u(ts+1)

    #pragma unroll 3
    for (int i = 2; i < nt + 2; i++) {
        load_u(lp, idx_sm[i], kw0, kw1, kw2, kw3, cur);   // u(ts+i)
        // emit term(ts+i-2): u_{c-2}(t) * u_{c-1}(t+1) * u_c(t+2)
        int a0 = __shfl_up_sync(0xffffffffu, p2[2], 1);
        int a1 = __shfl_up_sync(0xffffffffu, p2[3], 1);
        int b0 = __shfl_up_sync(0xffffffffu, p1[3], 1);
        acc[0] += a0    * b0    * cur[0];
        acc[1] += a1    * p1[0] * cur[1];
        acc[2] += p2[0] * p1[1] * cur[2];
        acc[3] += p2[1] * p1[2] * cur[3];
        p2[0] = p1[0]; p2[1] = p1[1]; p2[2] = p1[2]; p2[3] = p1[3];
        p1[0] = cur[0]; p1[1] = cur[1]; p1[2] = cur[2]; p1[3] = cur[3];
    }

    if (l >= 1) {                           // lane 0 is halo-only
        int obase = 124 * g + 4 * (l - 1);
        #pragma unroll
        for (int j = 0; j < 4; j++) {
            int oc = obase + j;
            if (oc < D_DIM) atomicAdd(&g_sum[oc], acc[j]);   // exact int, order-free
        }
    }
}

// ---------------- final quantize (tiny: 80KB traffic) ----------------
__global__ void k_final(float* __restrict__ out) {
    int d = blockIdx.x * blockDim.x + threadIdx.x;
    if (d >= D_DIM) return;
    float sample = -8.0f * (float)g_sum[d];      // exact: |.| < 2^24
    float x = sample * g_comb[d];
    out[d] = (x > 0.0f) ? 1.0f : -1.0f;
}

// ---------------- launch ----------------
extern "C" void kernel_launch(void* const* d_in, const int* in_sizes, int n_in,
                              void* d_out, int out_size) {
    const float* signals = (const float*)d_in[0];
    const float* feat    = (const float*)d_in[1];
    const float* keys_hv = (const float*)d_in[2];
    const float* lw      = (const float*)d_in[3];
    const float* feat_w  = (const float*)d_in[4];
    const float* feat_b  = (const float*)d_in[5];
    const float* mfcc_w  = (const float*)d_in[6];
    const float* mfcc_b  = (const float*)d_in[7];
    float* out = (float*)d_out;

    k_pre   <<<COMB_BLOCKS + PREP_BLOCKS, 256>>>(signals, keys_hv, lw,
                                                 feat, feat_w, feat_b, mfcc_w, mfcc_b);
    k_main  <<<dim3(NTILE, NCHUNK), THREADS_PB>>>();
    k_final <<<(D_DIM + 127) / 128, 128>>>(out);
}